// round 5
// baseline (speedup 1.0000x reference)
#include <cuda_runtime.h>
#include <cuda_bf16.h>

#define RES 128
#define FEAT 1024          // map_num * feat_dim = 128 * 8
#define VEC4_PER_ROW (FEAT / 4)   // 256

// One block per point, 256 threads; thread j handles float4 column j.
__global__ void __launch_bounds__(VEC4_PER_ROW, 8)
densemap_bilerp_kernel(const float* __restrict__ inp,
                       const float* __restrict__ emb,
                       float* __restrict__ out)
{
    const int p = blockIdx.x;

    // Every thread redundantly computes the point parameters (broadcast L1 hit).
    const float x0 = __ldg(&inp[2 * p + 0]) * (float)(RES - 1);
    const float x1 = __ldg(&inp[2 * p + 1]) * (float)(RES - 1);
    const float fl0 = floorf(x0);
    const float fl1 = floorf(x1);
    const int   i0  = (int)fl0;
    const int   i1  = (int)fl1;
    const float f0  = x0 - fl0;
    const float f1  = x1 - fl1;
    const float g0  = 1.0f - f0;
    const float g1  = 1.0f - f1;

    // bin_mask semantics from reference:
    //   n=0: (xi0,   xi1  )  w = g0*g1
    //   n=1: (xi0+1, xi1  )  w = f0*g1
    //   n=2: (xi0,   xi1+1)  w = g0*f1
    //   n=3: (xi0+1, xi1+1)  w = f0*f1
    const float w00 = g0 * g1;
    const float w10 = f0 * g1;
    const float w01 = g0 * f1;
    const float w11 = f0 * f1;

    const int base = i0 * RES + i1;
    const float4* __restrict__ r00 = (const float4*)(emb + (size_t)(base      ) * FEAT);
    const float4* __restrict__ r10 = (const float4*)(emb + (size_t)(base + RES) * FEAT);
    const float4* __restrict__ r01 = (const float4*)(emb + (size_t)(base +   1) * FEAT);
    const float4* __restrict__ r11 = (const float4*)(emb + (size_t)(base + RES + 1) * FEAT);

    const int c = threadIdx.x;   // 0..255

    // 4 independent 16B loads -> good MLP; all warp-coalesced within a row.
    const float4 a = __ldg(r00 + c);
    const float4 b = __ldg(r10 + c);
    const float4 d = __ldg(r01 + c);
    const float4 e = __ldg(r11 + c);

    float4 o;
    o.x = a.x * w00 + b.x * w10 + d.x * w01 + e.x * w11;
    o.y = a.y * w00 + b.y * w10 + d.y * w01 + e.y * w11;
    o.z = a.z * w00 + b.z * w10 + d.z * w01 + e.z * w11;
    o.w = a.w * w00 + b.w * w10 + d.w * w01 + e.w * w11;

    // Streaming store: keep the 256MB output stream from evicting the 64MB
    // embedding table out of L2.
    __stcs((float4*)(out + (size_t)p * FEAT) + c, o);
}

extern "C" void kernel_launch(void* const* d_in, const int* in_sizes, int n_in,
                              void* d_out, int out_size)
{
    const float* inp = (const float*)d_in[0];   // [batch, 2] float32
    const float* emb = (const float*)d_in[1];   // [16384, 1024] float32
    float* out = (float*)d_out;                 // [batch, 1024] float32

    const int n_points = in_sizes[0] / 2;

    densemap_bilerp_kernel<<<n_points, VEC4_PER_ROW>>>(inp, emb, out);
}

// round 6
// speedup vs baseline: 1.0451x; 1.0451x over previous
#include <cuda_runtime.h>
#include <cuda_bf16.h>

#define RES   128
#define FEAT  1024               // map_num * feat_dim
#define NCELL (RES * RES)        // 16384
#define NPTS_MAX 65536

// Scratch (allocation-free: __device__ globals)
__device__ int g_count[NCELL];
__device__ int g_start[NCELL];
__device__ int g_cursor[NCELL];
__device__ int g_sorted[NPTS_MAX];

__device__ __forceinline__ int cell_of(const float* __restrict__ inp, int p) {
    const float x0 = inp[2 * p + 0] * (float)(RES - 1);
    const float x1 = inp[2 * p + 1] * (float)(RES - 1);
    const int i0 = (int)floorf(x0);
    const int i1 = (int)floorf(x1);
    return i0 * RES + i1;        // i0,i1 in [0,126] for u in [0,1)
}

__global__ void zero_kernel() {
    const int i = blockIdx.x * blockDim.x + threadIdx.x;
    if (i < NCELL) g_count[i] = 0;
}

__global__ void hist_kernel(const float* __restrict__ inp, int n) {
    const int p = blockIdx.x * blockDim.x + threadIdx.x;
    if (p < n) atomicAdd(&g_count[cell_of(inp, p)], 1);
}

// Single-block exclusive scan over 16384 bins: 1024 threads x 16 bins each.
__global__ void scan_kernel() {
    __shared__ int sh[1024];
    const int t = threadIdx.x;

    int local[16];
    int sum = 0;
    #pragma unroll
    for (int i = 0; i < 16; i++) { local[i] = sum; sum += g_count[t * 16 + i]; }

    sh[t] = sum;
    __syncthreads();
    for (int off = 1; off < 1024; off <<= 1) {
        const int v = (t >= off) ? sh[t - off] : 0;
        __syncthreads();
        sh[t] += v;
        __syncthreads();
    }
    const int excl = sh[t] - sum;

    #pragma unroll
    for (int i = 0; i < 16; i++) {
        const int b = t * 16 + i;
        const int s = excl + local[i];
        g_start[b]  = s;
        g_cursor[b] = s;
    }
}

__global__ void scatter_kernel(const float* __restrict__ inp, int n) {
    const int p = blockIdx.x * blockDim.x + threadIdx.x;
    if (p < n) {
        const int c = cell_of(inp, p);
        const int pos = atomicAdd(&g_cursor[c], 1);
        g_sorted[pos] = p;
    }
}

// One block per cell. Load the 4 corner rows once into registers, then
// stream every point that falls in this cell.
__global__ void __launch_bounds__(256)
cell_bilerp_kernel(const float* __restrict__ inp,
                   const float* __restrict__ emb,
                   float* __restrict__ out)
{
    const int cell = blockIdx.x;
    const int n = g_count[cell];
    if (n == 0) return;                    // includes all i0==127 / i1==127 cells
    const int start = g_start[cell];

    const int c  = threadIdx.x;            // float4 column 0..255
    const int i0 = cell >> 7;
    const int i1 = cell & (RES - 1);

    // cell == i0*RES + i1 == embedding row index of corner (i0,i1)
    const float4 a = __ldg((const float4*)(emb + (size_t)(cell          ) * FEAT) + c); // (i0,  i1  )
    const float4 b = __ldg((const float4*)(emb + (size_t)(cell + RES    ) * FEAT) + c); // (i0+1,i1  )
    const float4 d = __ldg((const float4*)(emb + (size_t)(cell + 1      ) * FEAT) + c); // (i0,  i1+1)
    const float4 e = __ldg((const float4*)(emb + (size_t)(cell + RES + 1) * FEAT) + c); // (i0+1,i1+1)

    for (int k = 0; k < n; k++) {
        const int p = g_sorted[start + k];                 // warp-broadcast load

        const float x0 = __ldg(&inp[2 * p + 0]) * (float)(RES - 1);
        const float x1 = __ldg(&inp[2 * p + 1]) * (float)(RES - 1);
        const float f0 = x0 - (float)i0;                   // == x0 - floor(x0)
        const float f1 = x1 - (float)i1;
        const float g0 = 1.0f - f0;
        const float g1 = 1.0f - f1;
        const float w00 = g0 * g1, w10 = f0 * g1, w01 = g0 * f1, w11 = f0 * f1;

        float4 o;
        o.x = a.x * w00 + b.x * w10 + d.x * w01 + e.x * w11;
        o.y = a.y * w00 + b.y * w10 + d.y * w01 + e.y * w11;
        o.z = a.z * w00 + b.z * w10 + d.z * w01 + e.z * w11;
        o.w = a.w * w00 + b.w * w10 + d.w * w01 + e.w * w11;

        // Streaming store: keep the 256MB write stream from evicting the table.
        __stcs((float4*)(out + (size_t)p * FEAT) + c, o);
    }
}

extern "C" void kernel_launch(void* const* d_in, const int* in_sizes, int n_in,
                              void* d_out, int out_size)
{
    const float* inp = (const float*)d_in[0];   // [batch, 2]
    const float* emb = (const float*)d_in[1];   // [16384, 1024]
    float* out = (float*)d_out;                 // [batch, 1024]

    const int n_points = in_sizes[0] / 2;
    const int pt_blocks = (n_points + 255) / 256;

    zero_kernel   <<<(NCELL + 255) / 256, 256>>>();
    hist_kernel   <<<pt_blocks, 256>>>(inp, n_points);
    scan_kernel   <<<1, 1024>>>();
    scatter_kernel<<<pt_blocks, 256>>>(inp, n_points);
    cell_bilerp_kernel<<<NCELL, 256>>>(inp, emb, out);
}